// round 2
// baseline (speedup 1.0000x reference)
#include <cuda_runtime.h>

// out = clip(where(mask, 0.05, x), 0, 1)
// Since 0.05 is inside [0,1]:
//   Kernel A: out = saturate(x)          (pure streaming copy, float4)
//   Kernel B: overwrite crack pixels with 0.05 (stream-ordered after A)
//
// Reference quirk: inactive Bresenham steps have coords (-1,-1); JAX .at[]
// normalizes negative indices BEFORE mode='drop', so -1 wraps to 511.
// => every image with any line of nsteps < 511 also gets pixel (511,511) set.

#define HW 512
#define PLANE (HW * HW)          // 262144
#define LINES_PER_IMG 6
#define B_IMGS 32
#define N_LINES (B_IMGS * LINES_PER_IMG)  // 192
#define CRACK_VAL 0.05f

__global__ void saturate_copy_kernel(const float4* __restrict__ in,
                                     float4* __restrict__ out, int n4) {
    int i = blockIdx.x * blockDim.x + threadIdx.x;
    if (i < n4) {
        float4 v = in[i];
        v.x = __saturatef(v.x);
        v.y = __saturatef(v.y);
        v.z = __saturatef(v.z);
        v.w = __saturatef(v.w);
        out[i] = v;
    }
}

// One warp per line. Closed-form Bresenham matching the reference recurrence
// (emit-before-step; c1: 2err > -dy -> x+=sx; c2: 2err < dx -> y+=sy):
//   x-major (dx>=dy): point t = (x0 + sx*t, y0 + sy*floor((2t*dy + dx - 1)/(2dx)))
//   y-major:          symmetric with dx<->dy.
__global__ void crack_write_kernel(const int* __restrict__ ep,
                                   float* __restrict__ out) {
    int line = blockIdx.x;          // 0..191
    int lane = threadIdx.x;         // 0..31
    const int* e = ep + line * 4;
    int y0 = e[0], x0 = e[1], y1 = e[2], x1 = e[3];

    int dx = abs(x1 - x0);
    int dy = abs(y1 - y0);
    int sx = (x0 < x1) ? 1 : -1;
    int sy = (y0 < y1) ? 1 : -1;
    int ns = max(dx, dy);           // emits t = 0..ns inclusive

    int b = line / LINES_PER_IMG;
    float* base = out + (size_t)b * 3 * PLANE;

    // JAX negative-index wrap artifact: any inactive step writes (511,511).
    if (lane == 0 && ns < HW - 1) {
        int off = (HW - 1) * HW + (HW - 1);
        base[off]             = CRACK_VAL;
        base[off + PLANE]     = CRACK_VAL;
        base[off + 2 * PLANE] = CRACK_VAL;
    }

    for (int t = lane; t <= ns; t += 32) {
        int xx, yy;
        if (ns == 0) {
            xx = x0; yy = y0;
        } else if (dx >= dy) {      // x-major: dx > 0 here
            xx = x0 + sx * t;
            int k = (2 * t * dy + dx - 1) / (2 * dx);
            yy = y0 + sy * k;
        } else {                    // y-major: dy > 0 here
            yy = y0 + sy * t;
            int m = (2 * t * dx + dy - 1) / (2 * dy);
            xx = x0 + sx * m;
        }
        int off = yy * HW + xx;
        base[off]             = CRACK_VAL;
        base[off + PLANE]     = CRACK_VAL;
        base[off + 2 * PLANE] = CRACK_VAL;
    }
}

extern "C" void kernel_launch(void* const* d_in, const int* in_sizes, int n_in,
                              void* d_out, int out_size) {
    const float* x = (const float*)d_in[0];
    const int* endpoints = (const int*)d_in[1];
    float* out = (float*)d_out;

    int n4 = out_size / 4;  // 25,165,824 / 4 = 6,291,456 float4s
    int threads = 256;
    int blocks = (n4 + threads - 1) / threads;
    saturate_copy_kernel<<<blocks, threads>>>((const float4*)x, (float4*)out, n4);
    crack_write_kernel<<<N_LINES, 32>>>(endpoints, out);
}